// round 1
// baseline (speedup 1.0000x reference)
#include <cuda_runtime.h>

#define LN 1000000
#define DN 16
#define WN 64
#define KN 8
#define TILE 2048
#define XCOLS 2112   /* TILE + 64 */
#define THREADS 256
#define RPT 8        /* outputs per thread */

__device__ __forceinline__ unsigned long long pk2(float lo, float hi) {
    unsigned long long r;
    asm("mov.b64 %0, {%1, %2};" : "=l"(r) : "f"(lo), "f"(hi));
    return r;
}
__device__ __forceinline__ void ffma2(unsigned long long &a, unsigned long long xv, unsigned long long pv) {
    asm("fma.rn.f32x2 %0, %1, %2, %0;" : "+l"(a) : "l"(xv), "l"(pv));
}

extern __shared__ unsigned char smem_raw[];

__global__ void __launch_bounds__(THREADS, 1)
fullscan_main(const float* __restrict__ x, const float* __restrict__ P,
              float* __restrict__ out) {
    unsigned long long* p2s = (unsigned long long*)smem_raw;   // 8192 * 8B = 64 KB, layout [k*1024 + d*64 + w]
    float* xs = (float*)(smem_raw + 65536);                    // 16 * 2112 * 4B = 132 KB

    const int tid = threadIdx.x;
    const long long base = (long long)blockIdx.x * TILE;
    const int gstart = (int)base - 31;

    // P duplicated into packed pairs (p, p) so inner loop does LDS.128 broadcasts
    #pragma unroll
    for (int i = 0; i < 8192 / THREADS; i++) {
        int idx = tid + i * THREADS;
        float p = P[idx];
        p2s[idx] = pk2(p, p);
    }
    // x tile with index clamping (edge blocks; interior values there get
    // overwritten by the boundary kernel anyway)
    for (int d = 0; d < DN; d++) {
        const float* xrow = x + (size_t)d * LN;
        float* row = xs + d * XCOLS;
        for (int j = tid; j < XCOLS; j += THREADS) {
            int g = gstart + j;
            g = g < 0 ? 0 : (g > LN - 1 ? LN - 1 : g);
            row[j] = xrow[g];
        }
    }
    __syncthreads();

    unsigned long long acc[KN][4];
    #pragma unroll
    for (int k = 0; k < KN; k++)
        #pragma unroll
        for (int p = 0; p < 4; p++) acc[k][p] = 0ull;

    const int toff = tid * RPT;

    #pragma unroll 1
    for (int d = 0; d < DN; d++) {
        const float* xr = xs + d * XCOLS + toff;
        const unsigned long long* pr = p2s + d * WN;

        float w0, w1, w2, w3, w4, w5, w6, w7;
        {
            float4 v = *(const float4*)(xr);
            float4 u = *(const float4*)(xr + 4);
            w0 = v.x; w1 = v.y; w2 = v.z; w3 = v.w;
            w4 = u.x; w5 = u.y; w6 = u.z; w7 = u.w;
        }

        #pragma unroll 1
        for (int w = 0; w < WN; w += 4) {
            float4 nv = *(const float4*)(xr + w + 8);
            // substep s, pair p uses x values (xr[w+s+2p], xr[w+s+2p+1])
            unsigned long long a0 = pk2(w0, w1), a1 = pk2(w2, w3);
            unsigned long long a2 = pk2(w4, w5), a3 = pk2(w6, w7);
            unsigned long long b0 = pk2(w1, w2), b1 = pk2(w3, w4);
            unsigned long long b2 = pk2(w5, w6), b3 = pk2(w7, nv.x);
            unsigned long long c3 = pk2(nv.x, nv.y);
            unsigned long long d3 = pk2(nv.y, nv.z);

            #pragma unroll
            for (int k = 0; k < KN; k++) {
                const unsigned long long* pp = pr + k * (DN * WN) + w;
                ulonglong2 p01 = *(const ulonglong2*)(pp);
                ulonglong2 p23 = *(const ulonglong2*)(pp + 2);
                // s = 0
                ffma2(acc[k][0], a0, p01.x); ffma2(acc[k][1], a1, p01.x);
                ffma2(acc[k][2], a2, p01.x); ffma2(acc[k][3], a3, p01.x);
                // s = 1
                ffma2(acc[k][0], b0, p01.y); ffma2(acc[k][1], b1, p01.y);
                ffma2(acc[k][2], b2, p01.y); ffma2(acc[k][3], b3, p01.y);
                // s = 2
                ffma2(acc[k][0], a1, p23.x); ffma2(acc[k][1], a2, p23.x);
                ffma2(acc[k][2], a3, p23.x); ffma2(acc[k][3], c3, p23.x);
                // s = 3
                ffma2(acc[k][0], b1, p23.y); ffma2(acc[k][1], b2, p23.y);
                ffma2(acc[k][2], b3, p23.y); ffma2(acc[k][3], d3, p23.y);
            }
            // slide window by 4
            w0 = w4; w1 = w5; w2 = w6; w3 = w7;
            w4 = nv.x; w5 = nv.y; w6 = nv.z; w7 = nv.w;
        }
    }

    long long i0 = base + toff;
    if (i0 < LN) {  // i0 is a multiple of 8 and LN % 8 == 0 -> full vector in range
        #pragma unroll
        for (int k = 0; k < KN; k++) {
            float* o = out + (size_t)k * LN + i0;
            float2 f0 = *(float2*)&acc[k][0];
            float2 f1 = *(float2*)&acc[k][1];
            float2 f2 = *(float2*)&acc[k][2];
            float2 f3 = *(float2*)&acc[k][3];
            *(float4*)(o)     = make_float4(f0.x, f0.y, f1.x, f1.y);
            *(float4*)(o + 4) = make_float4(f2.x, f2.y, f3.x, f3.y);
        }
    }
}

// Exact reference boundary semantics:
//  left[k,j]  = sum_{m=0}^{32+j}  sum_d x[d,m]       * P[k,d,m],  j in [0,31)  -> out[k*L + j]
//  right[k,j] = sum_{m=j+1}^{63}  sum_d x[d,L-64+m]  * P[k,d,m],  j in [0,32)  -> out[k*L + (L-32) + j]
__global__ void fullscan_boundary(const float* __restrict__ x, const float* __restrict__ P,
                                  float* __restrict__ out) {
    __shared__ float tl[KN][WN];
    __shared__ float tr[KN][WN];
    int tid = threadIdx.x;          // 512 threads
    int k = tid >> 6, m = tid & 63;
    float sl = 0.f, sr = 0.f;
    #pragma unroll
    for (int d = 0; d < DN; d++) {
        float p = P[k * (DN * WN) + d * WN + m];
        sl += x[(size_t)d * LN + m] * p;
        sr += x[(size_t)d * LN + (LN - WN) + m] * p;
    }
    tl[k][m] = sl; tr[k][m] = sr;
    __syncthreads();
    if (m < 31) {
        float s = 0.f;
        for (int mm = 0; mm <= 32 + m; mm++) s += tl[k][mm];
        out[(size_t)k * LN + m] = s;
    }
    if (m < 32) {
        float s = 0.f;
        for (int mm = m + 1; mm < WN; mm++) s += tr[k][mm];
        out[(size_t)k * LN + (LN - 32) + m] = s;
    }
}

extern "C" void kernel_launch(void* const* d_in, const int* in_sizes, int n_in,
                              void* d_out, int out_size) {
    const float* x = (const float*)d_in[0];
    const float* P = (const float*)d_in[1];
    float* out = (float*)d_out;

    const int smem_bytes = 65536 + DN * XCOLS * 4;   // 200704 B
    cudaFuncSetAttribute(fullscan_main, cudaFuncAttributeMaxDynamicSharedMemorySize, smem_bytes);

    const int nblocks = (LN + TILE - 1) / TILE;      // 489
    fullscan_main<<<nblocks, THREADS, smem_bytes>>>(x, P, out);
    fullscan_boundary<<<1, 512>>>(x, P, out);
}